// round 10
// baseline (speedup 1.0000x reference)
#include <cuda_runtime.h>
#include <cuda_fp16.h>
#include <stdint.h>

// ---------------------------------------------------------------------------
// TopK Router, R10: single-pass fp16 HMMA GEMM + exact fp32 fixup of
// rank-ambiguous rows.
// logits = x @ W^T : [16384, 64], softmax, top-2.
// x: [4,4096,4096] f32   W: [64,4096] f32
// out f32: probs[16384*64] ++ indices[16384*2] ++ values[16384*2]
// k1: warps 0-3 consumers (32 rows x 64 experts), warps 4-7 producers.
//     Rows whose top-3 gaps < GAP_T get flagged for exact recompute.
// k2: fixup — 12 rows/block, exact fp32 logits via Wt[k][e] streamed from L2.
// ---------------------------------------------------------------------------

#define D_DIM   4096
#define E_DIM   64
#define NROWS   16384
#define ROWS_PER_BLK 128
#define THREADS 256
#define KC      64
#define NCHUNK  (D_DIM / KC)

#define GAP_T   4e-3f

// smem layout kernel1 (bytes)
#define A_TILE    (ROWS_PER_BLK * 128)       // 16384 B : 128 rows x 64 k fp16
#define SM_AHI(b) ((b) * A_TILE)
#define SM_W      (2 * A_TILE)               // 32768
#define W_TILE    (E_DIM * 128)              // 8192 B
#define SM_WHI(s) (SM_W + (s) * W_TILE)
#define SMEM_BYTES (SM_W + 3 * W_TILE)       // 57344

#define LG_STRIDE 68

#define SWZ(o) ((o) ^ (((o) >> 3) & 0x70))

__device__ __half g_Whi[E_DIM * D_DIM];      // W*64 in fp16, [e][k]
__device__ float  g_Wt [D_DIM * E_DIM];      // W exact f32, transposed [k][e]
__device__ int    g_ncand;
__device__ int    g_cand[NROWS];

// ---------------- PTX helpers -----------------------------------------------
__device__ __forceinline__ void cp16(uint32_t dst, const void* src) {
    asm volatile("cp.async.cg.shared.global [%0], [%1], 16;" :: "r"(dst), "l"(src));
}
__device__ __forceinline__ void cp_commit() {
    asm volatile("cp.async.commit_group;");
}
__device__ __forceinline__ void cp_wait1() {
    asm volatile("cp.async.wait_group 1;" ::: "memory");
}
__device__ __forceinline__ void cp_wait0() {
    asm volatile("cp.async.wait_group 0;" ::: "memory");
}
__device__ __forceinline__ void ldsm4(uint32_t addr, uint32_t* r) {
    asm volatile("ldmatrix.sync.aligned.m8n8.x4.shared.b16 {%0,%1,%2,%3}, [%4];"
                 : "=r"(r[0]), "=r"(r[1]), "=r"(r[2]), "=r"(r[3]) : "r"(addr));
}
__device__ __forceinline__ void mma16816(float* c,
                                         const uint32_t* a,
                                         uint32_t b0, uint32_t b1) {
    asm volatile(
        "mma.sync.aligned.m16n8k16.row.col.f32.f16.f16.f32 "
        "{%0,%1,%2,%3}, {%4,%5,%6,%7}, {%8,%9}, {%0,%1,%2,%3};"
        : "+f"(c[0]), "+f"(c[1]), "+f"(c[2]), "+f"(c[3])
        : "r"(a[0]), "r"(a[1]), "r"(a[2]), "r"(a[3]), "r"(b0), "r"(b1));
}

// ---------------- prep kernel: build Whi + Wt, reset candidate count ----------
__global__ void prep_W(const float* __restrict__ W) {
    int i = blockIdx.x * blockDim.x + threadIdx.x;   // 0 .. 262143
    if (i == 0) g_ncand = 0;
    float v = W[i];
    g_Whi[i] = __float2half_rn(v * 64.0f);
    int e = i >> 12, k = i & 4095;
    g_Wt[k * 64 + e] = v;
}

// ---------------- producer helpers (pt in [0,128)) ----------------------------
__device__ __forceinline__ void ldg_chunk(float R[8][8], const float* __restrict__ x,
                                          int row0, int c0, int pt) {
#pragma unroll
    for (int it = 0; it < 8; ++it) {
        int id = it * 128 + pt;
        int row = id >> 3, g = id & 7;
        const float4* p = (const float4*)(x + (size_t)(row0 + row) * D_DIM + c0 + g * 8);
        float4 a = p[0], b = p[1];
        R[it][0]=a.x; R[it][1]=a.y; R[it][2]=a.z; R[it][3]=a.w;
        R[it][4]=b.x; R[it][5]=b.y; R[it][6]=b.z; R[it][7]=b.w;
    }
}
__device__ __forceinline__ void convert_chunk(const float R[8][8], char* smem,
                                              int buf, int pt) {
#pragma unroll
    for (int it = 0; it < 8; ++it) {
        int id = it * 128 + pt;
        int row = id >> 3, g = id & 7;
        uint32_t hv[4];
#pragma unroll
        for (int j = 0; j < 4; ++j) {
            __half2 hh = __floats2half2_rn(R[it][2*j] * 16.0f, R[it][2*j+1] * 16.0f);
            hv[j] = *reinterpret_cast<uint32_t*>(&hh);
        }
        uint32_t off = SWZ(row * 128 + g * 16);
        *(uint4*)(smem + SM_AHI(buf) + off) = make_uint4(hv[0], hv[1], hv[2], hv[3]);
    }
}
__device__ __forceinline__ void cpW_chunk(uint32_t sbase, int c, int pt) {
    const int slot = c % 3;
#pragma unroll
    for (int it = 0; it < 4; ++it) {
        int id = it * 128 + pt;          // 0..511
        int e = id >> 3, q = id & 7;
        uint32_t dst = sbase + SM_WHI(slot) + SWZ(e * 128 + q * 16);
        const __half* src = g_Whi + (size_t)e * D_DIM + c * KC + q * 8;
        cp16(dst, src);
    }
    cp_commit();
}

// ---------------- main kernel -------------------------------------------------
__global__ void __launch_bounds__(THREADS, 1)
router_kernel(const float* __restrict__ x, float* __restrict__ out)
{
    extern __shared__ char smem[];
    const int t    = threadIdx.x;
    const int lane = t & 31;
    const int row0 = blockIdx.x * ROWS_PER_BLK;
    const uint32_t sbase = (uint32_t)__cvta_generic_to_shared(smem);
    const bool consumer = (t < 128);

    const int lg = lane >> 3;
    const int li = lane & 7;

    const int wc = t >> 5;                    // 0..3 consumers, rows [32wc,+32)
    float acc[2][8][4];
#pragma unroll
    for (int m = 0; m < 2; ++m)
#pragma unroll
        for (int j = 0; j < 8; ++j)
#pragma unroll
            for (int q = 0; q < 4; ++q) acc[m][j][q] = 0.f;

    uint32_t aoffb[2];
#pragma unroll
    for (int m = 0; m < 2; ++m) {
        int arow = 32 * wc + 16 * m + li + ((lg & 1) ? 8 : 0);
        aoffb[m] = (uint32_t)(arow * 128 + ((lg & 2) ? 16 : 0));
    }
    const int berow = li + ((lg & 2) ? 8 : 0);
    const uint32_t boffb = (uint32_t)(berow * 128 + ((lg & 1) ? 16 : 0));

    const int pt = t - 128;
    float R[8][8];

    // ---- prologue (producers) ----
    if (!consumer) {
        ldg_chunk(R, x, row0, 0, pt);
        cpW_chunk(sbase, 0, pt);
        convert_chunk(R, smem, 0, pt);
        ldg_chunk(R, x, row0, KC, pt);
        cpW_chunk(sbase, 1, pt);
        cp_wait1();
    }
    __syncthreads();

    // ---- main loop (single hh pass) ----
    for (int c = 0; c < NCHUNK; ++c) {
        if (consumer) {
            const uint32_t ahi = sbase + SM_AHI(c & 1);
            const uint32_t whi = sbase + SM_WHI(c % 3);

            uint32_t fw[2][4][4];   // [buf][p][4]
#pragma unroll
            for (int p = 0; p < 4; ++p)
                ldsm4(whi + SWZ(boffb + (uint32_t)(p * 16 * 128)), fw[0][p]);
#pragma unroll
            for (int s = 0; s < 4; ++s) {
                uint32_t fa[2][4];
#pragma unroll
                for (int m = 0; m < 2; ++m)
                    ldsm4(ahi + SWZ(aoffb[m] + s * 32), fa[m]);
                if (s < 3) {
#pragma unroll
                    for (int p = 0; p < 4; ++p)
                        ldsm4(whi + SWZ(boffb + (uint32_t)(p * 16 * 128) + (s + 1) * 32),
                              fw[(s + 1) & 1][p]);
                }
#pragma unroll
                for (int p = 0; p < 4; ++p) {
                    const uint32_t* bh = fw[s & 1][p];
#pragma unroll
                    for (int m = 0; m < 2; ++m) {
                        mma16816(acc[m][2 * p],     fa[m], bh[0], bh[1]);
                        mma16816(acc[m][2 * p + 1], fa[m], bh[2], bh[3]);
                    }
                }
            }
        } else {
            if (c + 1 < NCHUNK) convert_chunk(R, smem, (c + 1) & 1, pt);
            if (c + 2 < NCHUNK) {
                ldg_chunk(R, x, row0, (c + 2) * KC, pt);
                cpW_chunk(sbase, c + 2, pt);
                cp_wait1();
            } else if (c + 1 < NCHUNK) {
                cp_wait0();
            }
        }
        __syncthreads();
    }

    // ---- epilogue: logits -> smem (reuse A region) ----
    float* lgm = (float*)smem;
    if (consumer) {
        const int r_in = lane >> 2;
        const int col  = 2 * (lane & 3);
        const float sc = 1.0f / 1024.0f;
#pragma unroll
        for (int m = 0; m < 2; ++m) {
            const int rb = 32 * wc + 16 * m + r_in;
#pragma unroll
            for (int j = 0; j < 8; ++j) {
                *(float2*)(lgm + rb * LG_STRIDE + 8 * j + col)
                    = make_float2(acc[m][j][0] * sc, acc[m][j][1] * sc);
                *(float2*)(lgm + (rb + 8) * LG_STRIDE + 8 * j + col)
                    = make_float2(acc[m][j][2] * sc, acc[m][j][3] * sc);
            }
        }
    }
    __syncthreads();

    if (t < ROWS_PER_BLK) {
        float l[64];
#pragma unroll
        for (int j = 0; j < 16; ++j) {
            float4 v = *(const float4*)(lgm + t * LG_STRIDE + 4 * j);
            l[4*j+0] = v.x; l[4*j+1] = v.y; l[4*j+2] = v.z; l[4*j+3] = v.w;
        }

        float mx = l[0];
#pragma unroll
        for (int j = 1; j < 64; ++j) mx = fmaxf(mx, l[j]);

        // top-3 (strict > keeps lowest index on ties, matching jax top_k)
        float v1 = -3.4e38f, v2 = -3.4e38f, v3 = -3.4e38f;
        int   i1 = 0,        i2 = 0;
#pragma unroll
        for (int j = 0; j < 64; ++j) {
            float lj = l[j];
            if (lj > v1)      { v3 = v2; v2 = v1; i2 = i1; v1 = lj; i1 = j; }
            else if (lj > v2) { v3 = v2; v2 = lj; i2 = j; }
            else if (lj > v3) { v3 = lj; }
        }

        float p[64], s = 0.f;
#pragma unroll
        for (int j = 0; j < 64; ++j) { p[j] = __expf(l[j] - mx); s += p[j]; }
        float inv = __fdividef(1.0f, s);

        const int grow = row0 + t;
        float* po = out + (size_t)grow * 64;
#pragma unroll
        for (int j = 0; j < 16; ++j) {
            float4 v;
            v.x = p[4*j+0] * inv; v.y = p[4*j+1] * inv;
            v.z = p[4*j+2] * inv; v.w = p[4*j+3] * inv;
            *(float4*)(po + 4 * j) = v;
        }
        float* io = out + (size_t)NROWS * 64;
        io[(size_t)grow * 2 + 0] = (float)i1;
        io[(size_t)grow * 2 + 1] = (float)i2;
        float* vo = out + (size_t)NROWS * 64 + (size_t)NROWS * 2;
        vo[(size_t)grow * 2 + 0] = __expf(v1 - mx) * inv;
        vo[(size_t)grow * 2 + 1] = __expf(v2 - mx) * inv;

        // flag ambiguous rankings for exact recompute
        if ((v1 - v2) < GAP_T || (v2 - v3) < GAP_T) {
            int slot = atomicAdd(&g_ncand, 1);
            g_cand[slot] = grow;
        }
    }
}

// ---------------- fixup kernel: exact fp32 recompute of flagged rows ----------
#define FB 12                                // rows per block
#define FIX_SMEM (FB * D_DIM * 4)            // 196608 B

__global__ void __launch_bounds__(256, 1)
fixup_kernel(const float* __restrict__ x, float* __restrict__ out)
{
    extern __shared__ float fs[];            // xs[FB][4096], later reduce buf
    const int n = g_ncand;
    const int t = threadIdx.x;

    for (int g = blockIdx.x; g * FB < n; g += gridDim.x) {
        const int nb = min(FB, n - g * FB);
        __syncthreads();                     // smem reuse across groups

        // load x rows to smem
        for (int r = 0; r < nb; ++r) {
            const int row = g_cand[g * FB + r];
            const float4* src = (const float4*)(x + (size_t)row * D_DIM);
            float4* dst = (float4*)(fs + r * D_DIM);
            for (int i = t; i < D_DIM / 4; i += 256) dst[i] = src[i];
        }
        __syncthreads();

        // exact logits: thread (e = t&63, kq = t>>6), acc over 1024 k
        const int e  = t & 63;
        const int kq = t >> 6;
        float acc[FB];
#pragma unroll
        for (int r = 0; r < FB; ++r) acc[r] = 0.f;
        for (int k4 = kq * 256; k4 < kq * 256 + 256; ++k4) {
            const int k = 4 * k4;
            float w0 = g_Wt[(k + 0) * 64 + e];
            float w1 = g_Wt[(k + 1) * 64 + e];
            float w2 = g_Wt[(k + 2) * 64 + e];
            float w3 = g_Wt[(k + 3) * 64 + e];
#pragma unroll
            for (int r = 0; r < FB; ++r) {
                float4 xv = *(const float4*)(fs + r * D_DIM + k);
                acc[r] += xv.x * w0;
                acc[r] += xv.y * w1;
                acc[r] += xv.z * w2;
                acc[r] += xv.w * w3;
            }
        }
        __syncthreads();                     // xs no longer needed

        // reduce 4 partials: red[kq][r][e]
        float* red = fs;
#pragma unroll
        for (int r = 0; r < FB; ++r) red[(kq * FB + r) * 64 + e] = acc[r];
        __syncthreads();
        float* lgr = fs + 4 * FB * 64;       // final logits [r][e]
        if (t < 64) {
            for (int r = 0; r < nb; ++r) {
                float s = red[(0 * FB + r) * 64 + t] + red[(1 * FB + r) * 64 + t]
                        + red[(2 * FB + r) * 64 + t] + red[(3 * FB + r) * 64 + t];
                lgr[r * 64 + t] = s;
            }
        }
        __syncthreads();

        // per-row softmax + top-2, overwrite outputs
        if (t < nb) {
            const int row = g_cand[g * FB + t];
            float l[64];
#pragma unroll
            for (int j = 0; j < 64; ++j) l[j] = lgr[t * 64 + j];

            float mx = l[0];
#pragma unroll
            for (int j = 1; j < 64; ++j) mx = fmaxf(mx, l[j]);

            float v1 = -3.4e38f, v2 = -3.4e38f;
            int   i1 = 0,        i2 = 0;
#pragma unroll
            for (int j = 0; j < 64; ++j) {
                float lj = l[j];
                if (lj > v1)      { v2 = v1; i2 = i1; v1 = lj; i1 = j; }
                else if (lj > v2) { v2 = lj; i2 = j; }
            }

            float p[64], s = 0.f;
#pragma unroll
            for (int j = 0; j < 64; ++j) { p[j] = __expf(l[j] - mx); s += p[j]; }
            float inv = __fdividef(1.0f, s);

            float* po = out + (size_t)row * 64;
#pragma unroll
            for (int j = 0; j < 64; ++j) po[j] = p[j] * inv;

            float* io = out + (size_t)NROWS * 64;
            io[(size_t)row * 2 + 0] = (float)i1;
            io[(size_t)row * 2 + 1] = (float)i2;
            float* vo = out + (size_t)NROWS * 64 + (size_t)NROWS * 2;
            vo[(size_t)row * 2 + 0] = __expf(v1 - mx) * inv;
            vo[(size_t)row * 2 + 1] = __expf(v2 - mx) * inv;
        }
    }
}

// ---------------------------------------------------------------------------
extern "C" void kernel_launch(void* const* d_in, const int* in_sizes, int n_in,
                              void* d_out, int out_size) {
    const float* x = (const float*)d_in[0];
    const float* W = (const float*)d_in[1];
    float* out = (float*)d_out;

    prep_W<<<(E_DIM * D_DIM) / 256, 256>>>(W);

    cudaFuncSetAttribute(router_kernel,
                         cudaFuncAttributeMaxDynamicSharedMemorySize, SMEM_BYTES);
    router_kernel<<<NROWS / ROWS_PER_BLK, THREADS, SMEM_BYTES>>>(x, out);

    cudaFuncSetAttribute(fixup_kernel,
                         cudaFuncAttributeMaxDynamicSharedMemorySize, FIX_SMEM + 1024);
    fixup_kernel<<<64, 256, FIX_SMEM + 1024>>>(x, out);
}

// round 11
// speedup vs baseline: 2.8524x; 2.8524x over previous
#include <cuda_runtime.h>
#include <cuda_fp16.h>
#include <stdint.h>

// ---------------------------------------------------------------------------
// TopK Router, R11: single-pass fp16 HMMA GEMM + warp-per-row exact
// contender re-ranking for ambiguous rows.
// logits = x @ W^T : [16384, 64], softmax, top-2.
// x: [4,4096,4096] f32   W: [64,4096] f32
// out f32: probs[16384*64] ++ indices[16384*2] ++ values[16384*2]
// ---------------------------------------------------------------------------

#define D_DIM   4096
#define E_DIM   64
#define NROWS   16384
#define ROWS_PER_BLK 128
#define THREADS 256
#define KC      64
#define NCHUNK  (D_DIM / KC)

#define GAP_T    4e-3f         // router flag threshold (logit units)
#define BAND_MUL 0.9940180f    // exp(-6e-3): fixup contender band

// smem layout kernel1 (bytes)
#define A_TILE    (ROWS_PER_BLK * 128)       // 16384 B : 128 rows x 64 k fp16
#define SM_AHI(b) ((b) * A_TILE)
#define SM_W      (2 * A_TILE)               // 32768
#define W_TILE    (E_DIM * 128)              // 8192 B
#define SM_WHI(s) (SM_W + (s) * W_TILE)
#define SMEM_BYTES (SM_W + 3 * W_TILE)       // 57344

#define LG_STRIDE 68

#define SWZ(o) ((o) ^ (((o) >> 3) & 0x70))

__device__ __half g_Whi[E_DIM * D_DIM];      // W*64 in fp16, [e][k]
__device__ int    g_ncand;
__device__ int    g_cand[NROWS];

// ---------------- PTX helpers -----------------------------------------------
__device__ __forceinline__ void cp16(uint32_t dst, const void* src) {
    asm volatile("cp.async.cg.shared.global [%0], [%1], 16;" :: "r"(dst), "l"(src));
}
__device__ __forceinline__ void cp_commit() {
    asm volatile("cp.async.commit_group;");
}
__device__ __forceinline__ void cp_wait1() {
    asm volatile("cp.async.wait_group 1;" ::: "memory");
}
__device__ __forceinline__ void cp_wait0() {
    asm volatile("cp.async.wait_group 0;" ::: "memory");
}
__device__ __forceinline__ void ldsm4(uint32_t addr, uint32_t* r) {
    asm volatile("ldmatrix.sync.aligned.m8n8.x4.shared.b16 {%0,%1,%2,%3}, [%4];"
                 : "=r"(r[0]), "=r"(r[1]), "=r"(r[2]), "=r"(r[3]) : "r"(addr));
}
__device__ __forceinline__ void mma16816(float* c,
                                         const uint32_t* a,
                                         uint32_t b0, uint32_t b1) {
    asm volatile(
        "mma.sync.aligned.m16n8k16.row.col.f32.f16.f16.f32 "
        "{%0,%1,%2,%3}, {%4,%5,%6,%7}, {%8,%9}, {%0,%1,%2,%3};"
        : "+f"(c[0]), "+f"(c[1]), "+f"(c[2]), "+f"(c[3])
        : "r"(a[0]), "r"(a[1]), "r"(a[2]), "r"(a[3]), "r"(b0), "r"(b1));
}

// ---------------- prep kernel (coalesced only) --------------------------------
__global__ void prep_W(const float* __restrict__ W) {
    int i = blockIdx.x * blockDim.x + threadIdx.x;   // 0 .. 262143
    if (i == 0) g_ncand = 0;
    g_Whi[i] = __float2half_rn(W[i] * 64.0f);
}

// ---------------- producer helpers (pt in [0,128)) ----------------------------
__device__ __forceinline__ void ldg_chunk(float R[8][8], const float* __restrict__ x,
                                          int row0, int c0, int pt) {
#pragma unroll
    for (int it = 0; it < 8; ++it) {
        int id = it * 128 + pt;
        int row = id >> 3, g = id & 7;
        const float4* p = (const float4*)(x + (size_t)(row0 + row) * D_DIM + c0 + g * 8);
        float4 a = p[0], b = p[1];
        R[it][0]=a.x; R[it][1]=a.y; R[it][2]=a.z; R[it][3]=a.w;
        R[it][4]=b.x; R[it][5]=b.y; R[it][6]=b.z; R[it][7]=b.w;
    }
}
__device__ __forceinline__ void convert_chunk(const float R[8][8], char* smem,
                                              int buf, int pt) {
#pragma unroll
    for (int it = 0; it < 8; ++it) {
        int id = it * 128 + pt;
        int row = id >> 3, g = id & 7;
        uint32_t hv[4];
#pragma unroll
        for (int j = 0; j < 4; ++j) {
            __half2 hh = __floats2half2_rn(R[it][2*j] * 16.0f, R[it][2*j+1] * 16.0f);
            hv[j] = *reinterpret_cast<uint32_t*>(&hh);
        }
        uint32_t off = SWZ(row * 128 + g * 16);
        *(uint4*)(smem + SM_AHI(buf) + off) = make_uint4(hv[0], hv[1], hv[2], hv[3]);
    }
}
__device__ __forceinline__ void cpW_chunk(uint32_t sbase, int c, int pt) {
    const int slot = c % 3;
#pragma unroll
    for (int it = 0; it < 4; ++it) {
        int id = it * 128 + pt;          // 0..511
        int e = id >> 3, q = id & 7;
        uint32_t dst = sbase + SM_WHI(slot) + SWZ(e * 128 + q * 16);
        const __half* src = g_Whi + (size_t)e * D_DIM + c * KC + q * 8;
        cp16(dst, src);
    }
    cp_commit();
}

// ---------------- main kernel -------------------------------------------------
__global__ void __launch_bounds__(THREADS, 1)
router_kernel(const float* __restrict__ x, float* __restrict__ out)
{
    extern __shared__ char smem[];
    const int t    = threadIdx.x;
    const int lane = t & 31;
    const int row0 = blockIdx.x * ROWS_PER_BLK;
    const uint32_t sbase = (uint32_t)__cvta_generic_to_shared(smem);
    const bool consumer = (t < 128);

    const int lg = lane >> 3;
    const int li = lane & 7;

    const int wc = t >> 5;                    // 0..3 consumers, rows [32wc,+32)
    float acc[2][8][4];
#pragma unroll
    for (int m = 0; m < 2; ++m)
#pragma unroll
        for (int j = 0; j < 8; ++j)
#pragma unroll
            for (int q = 0; q < 4; ++q) acc[m][j][q] = 0.f;

    uint32_t aoffb[2];
#pragma unroll
    for (int m = 0; m < 2; ++m) {
        int arow = 32 * wc + 16 * m + li + ((lg & 1) ? 8 : 0);
        aoffb[m] = (uint32_t)(arow * 128 + ((lg & 2) ? 16 : 0));
    }
    const int berow = li + ((lg & 2) ? 8 : 0);
    const uint32_t boffb = (uint32_t)(berow * 128 + ((lg & 1) ? 16 : 0));

    const int pt = t - 128;
    float R[8][8];

    // ---- prologue (producers) ----
    if (!consumer) {
        ldg_chunk(R, x, row0, 0, pt);
        cpW_chunk(sbase, 0, pt);
        convert_chunk(R, smem, 0, pt);
        ldg_chunk(R, x, row0, KC, pt);
        cpW_chunk(sbase, 1, pt);
        cp_wait1();
    }
    __syncthreads();

    // ---- main loop (single hh pass) ----
    for (int c = 0; c < NCHUNK; ++c) {
        if (consumer) {
            const uint32_t ahi = sbase + SM_AHI(c & 1);
            const uint32_t whi = sbase + SM_WHI(c % 3);

            uint32_t fw[2][4][4];
#pragma unroll
            for (int p = 0; p < 4; ++p)
                ldsm4(whi + SWZ(boffb + (uint32_t)(p * 16 * 128)), fw[0][p]);
#pragma unroll
            for (int s = 0; s < 4; ++s) {
                uint32_t fa[2][4];
#pragma unroll
                for (int m = 0; m < 2; ++m)
                    ldsm4(ahi + SWZ(aoffb[m] + s * 32), fa[m]);
                if (s < 3) {
#pragma unroll
                    for (int p = 0; p < 4; ++p)
                        ldsm4(whi + SWZ(boffb + (uint32_t)(p * 16 * 128) + (s + 1) * 32),
                              fw[(s + 1) & 1][p]);
                }
#pragma unroll
                for (int p = 0; p < 4; ++p) {
                    const uint32_t* bh = fw[s & 1][p];
#pragma unroll
                    for (int m = 0; m < 2; ++m) {
                        mma16816(acc[m][2 * p],     fa[m], bh[0], bh[1]);
                        mma16816(acc[m][2 * p + 1], fa[m], bh[2], bh[3]);
                    }
                }
            }
        } else {
            if (c + 1 < NCHUNK) convert_chunk(R, smem, (c + 1) & 1, pt);
            if (c + 2 < NCHUNK) {
                ldg_chunk(R, x, row0, (c + 2) * KC, pt);
                cpW_chunk(sbase, c + 2, pt);
                cp_wait1();
            } else if (c + 1 < NCHUNK) {
                cp_wait0();
            }
        }
        __syncthreads();
    }

    // ---- epilogue: logits -> smem (reuse A region) ----
    float* lgm = (float*)smem;
    if (consumer) {
        const int r_in = lane >> 2;
        const int col  = 2 * (lane & 3);
        const float sc = 1.0f / 1024.0f;
#pragma unroll
        for (int m = 0; m < 2; ++m) {
            const int rb = 32 * wc + 16 * m + r_in;
#pragma unroll
            for (int j = 0; j < 8; ++j) {
                *(float2*)(lgm + rb * LG_STRIDE + 8 * j + col)
                    = make_float2(acc[m][j][0] * sc, acc[m][j][1] * sc);
                *(float2*)(lgm + (rb + 8) * LG_STRIDE + 8 * j + col)
                    = make_float2(acc[m][j][2] * sc, acc[m][j][3] * sc);
            }
        }
    }
    __syncthreads();

    if (t < ROWS_PER_BLK) {
        float l[64];
#pragma unroll
        for (int j = 0; j < 16; ++j) {
            float4 v = *(const float4*)(lgm + t * LG_STRIDE + 4 * j);
            l[4*j+0] = v.x; l[4*j+1] = v.y; l[4*j+2] = v.z; l[4*j+3] = v.w;
        }

        float mx = l[0];
#pragma unroll
        for (int j = 1; j < 64; ++j) mx = fmaxf(mx, l[j]);

        // top-3 (strict > keeps lowest index on ties, matching jax top_k)
        float v1 = -3.4e38f, v2 = -3.4e38f, v3 = -3.4e38f;
        int   i1 = 0,        i2 = 0;
#pragma unroll
        for (int j = 0; j < 64; ++j) {
            float lj = l[j];
            if (lj > v1)      { v3 = v2; v2 = v1; i2 = i1; v1 = lj; i1 = j; }
            else if (lj > v2) { v3 = v2; v2 = lj; i2 = j; }
            else if (lj > v3) { v3 = lj; }
        }

        float p[64], s = 0.f;
#pragma unroll
        for (int j = 0; j < 64; ++j) { p[j] = __expf(l[j] - mx); s += p[j]; }
        float inv = __fdividef(1.0f, s);

        const int grow = row0 + t;
        float* po = out + (size_t)grow * 64;
#pragma unroll
        for (int j = 0; j < 16; ++j) {
            float4 v;
            v.x = p[4*j+0] * inv; v.y = p[4*j+1] * inv;
            v.z = p[4*j+2] * inv; v.w = p[4*j+3] * inv;
            *(float4*)(po + 4 * j) = v;
        }
        float* io = out + (size_t)NROWS * 64;
        io[(size_t)grow * 2 + 0] = (float)i1;
        io[(size_t)grow * 2 + 1] = (float)i2;
        float* vo = out + (size_t)NROWS * 64 + (size_t)NROWS * 2;
        vo[(size_t)grow * 2 + 0] = __expf(v1 - mx) * inv;
        vo[(size_t)grow * 2 + 1] = __expf(v2 - mx) * inv;

        if ((v1 - v2) < GAP_T || (v2 - v3) < GAP_T) {
            int slot = atomicAdd(&g_ncand, 1);
            g_cand[slot] = grow;
        }
    }
}

// ---------------- fixup: one warp per flagged row ------------------------------
__global__ void __launch_bounds__(256, 1)
fixup_kernel(const float* __restrict__ x, const float* __restrict__ W,
             float* __restrict__ out)
{
    const int n    = g_ncand;
    const int lane = threadIdx.x & 31;
    const int gw   = (blockIdx.x * blockDim.x + threadIdx.x) >> 5;
    const int nw   = (gridDim.x * blockDim.x) >> 5;

    for (int ci = gw; ci < n; ci += nw) {
        const int row = g_cand[ci];
        const float* probs = out + (size_t)row * 64;

        // each lane holds probs[lane], probs[lane+32]
        float p0 = probs[lane];
        float p1 = probs[lane + 32];

        // warp top-2 of probs: per-lane (m1 >= m2), merge via shfl
        float m1 = fmaxf(p0, p1), m2 = fminf(p0, p1);
#pragma unroll
        for (int o = 16; o > 0; o >>= 1) {
            float o1 = __shfl_xor_sync(0xFFFFFFFF, m1, o);
            float o2 = __shfl_xor_sync(0xFFFFFFFF, m2, o);
            float n1 = fmaxf(m1, o1);
            float n2 = fminf(fmaxf(m1, o2), fmaxf(o1, m2));  // 2nd of union
            n2 = fmaxf(n2, fminf(m1, o1));
            m1 = n1; m2 = n2;
        }
        const float thresh = m2 * BAND_MUL;

        unsigned b0 = __ballot_sync(0xFFFFFFFF, p0 >= thresh);
        unsigned b1 = __ballot_sync(0xFFFFFFFF, p1 >= thresh);

        const float4* xr = (const float4*)(x + (size_t)row * D_DIM);

        float best1 = -3.4e38f, best2 = -3.4e38f;
        int   bi1 = -1,         bi2 = -1;

        for (int e = 0; e < 64; ++e) {
            bool cand = (e < 32) ? ((b0 >> e) & 1u) : ((b1 >> (e - 32)) & 1u);
            if (!cand) continue;   // warp-uniform (ballot result)
            const float4* wr = (const float4*)(W + (size_t)e * D_DIM);
            float a = 0.f;
            for (int i = lane; i < D_DIM / 4; i += 32) {
                float4 xv = xr[i];
                float4 wv = wr[i];
                a += xv.x * wv.x;
                a += xv.y * wv.y;
                a += xv.z * wv.z;
                a += xv.w * wv.w;
            }
#pragma unroll
            for (int o = 16; o > 0; o >>= 1)
                a += __shfl_xor_sync(0xFFFFFFFF, a, o);
            // ascending e + strict > implements lowest-index tie-break
            if (a > best1)      { best2 = best1; bi2 = bi1; best1 = a; bi1 = e; }
            else if (a > best2) { best2 = a; bi2 = e; }
        }

        if (lane == 0) {
            float* io = out + (size_t)NROWS * 64;
            io[(size_t)row * 2 + 0] = (float)bi1;
            io[(size_t)row * 2 + 1] = (float)bi2;
            float* vo = out + (size_t)NROWS * 64 + (size_t)NROWS * 2;
            vo[(size_t)row * 2 + 0] = probs[bi1];
            vo[(size_t)row * 2 + 1] = probs[bi2];
        }
    }
}

// ---------------------------------------------------------------------------
extern "C" void kernel_launch(void* const* d_in, const int* in_sizes, int n_in,
                              void* d_out, int out_size) {
    const float* x = (const float*)d_in[0];
    const float* W = (const float*)d_in[1];
    float* out = (float*)d_out;

    prep_W<<<(E_DIM * D_DIM) / 256, 256>>>(W);

    cudaFuncSetAttribute(router_kernel,
                         cudaFuncAttributeMaxDynamicSharedMemorySize, SMEM_BYTES);
    router_kernel<<<NROWS / ROWS_PER_BLK, THREADS, SMEM_BYTES>>>(x, out);

    fixup_kernel<<<256, 256>>>(x, W, out);
}

// round 12
// speedup vs baseline: 2.9039x; 1.0181x over previous
#include <cuda_runtime.h>
#include <cuda_fp16.h>
#include <stdint.h>

// ---------------------------------------------------------------------------
// TopK Router, R12: single-pass fp16 HMMA GEMM, x streamed via deep cp.async
// pipeline (3 chunks ahead), + warp-per-row exact contender re-ranking.
// logits = x @ W^T : [16384, 64], softmax, top-2.
// x: [4,4096,4096] f32   W: [64,4096] f32
// out f32: probs[16384*64] ++ indices[16384*2] ++ values[16384*2]
// ---------------------------------------------------------------------------

#define D_DIM   4096
#define E_DIM   64
#define NROWS   16384
#define ROWS_PER_BLK 128
#define THREADS 256
#define KC      64
#define NCHUNK  (D_DIM / KC)

#define GAP_T    4e-3f
#define BAND_MUL 0.9940180f    // exp(-6e-3)

// smem layout (bytes)
#define XS_SLOT   (ROWS_PER_BLK * 68 * 4)    // 34816 B : 128 rows x 64 f32, stride 68
#define SM_XS(s)  ((s) * XS_SLOT)            // 3 slots : 104448
#define A_TILE    (ROWS_PER_BLK * 128)       // 16384 B : 128 rows x 64 k fp16
#define SM_A(b)   (3 * XS_SLOT + (b) * A_TILE)
#define W_TILE    (E_DIM * 128)              // 8192 B
#define SM_W(s)   (3 * XS_SLOT + 2 * A_TILE + (s) * W_TILE)   // 4 slots
#define SMEM_BYTES (3 * XS_SLOT + 2 * A_TILE + 4 * W_TILE)    // 169984

#define LG_STRIDE 68                          // logits reuse XS region

#define SWZ(o) ((o) ^ (((o) >> 3) & 0x70))

__device__ __half g_Whi[E_DIM * D_DIM];      // W*64 in fp16, [e][k]
__device__ int    g_ncand;
__device__ int    g_cand[NROWS];

// ---------------- PTX helpers -----------------------------------------------
__device__ __forceinline__ void cp16(uint32_t dst, const void* src) {
    asm volatile("cp.async.cg.shared.global [%0], [%1], 16;" :: "r"(dst), "l"(src));
}
__device__ __forceinline__ void cp_commit() {
    asm volatile("cp.async.commit_group;");
}
__device__ __forceinline__ void cp_wait1() {
    asm volatile("cp.async.wait_group 1;" ::: "memory");
}
__device__ __forceinline__ void cp_wait0() {
    asm volatile("cp.async.wait_group 0;" ::: "memory");
}
__device__ __forceinline__ void ldsm4(uint32_t addr, uint32_t* r) {
    asm volatile("ldmatrix.sync.aligned.m8n8.x4.shared.b16 {%0,%1,%2,%3}, [%4];"
                 : "=r"(r[0]), "=r"(r[1]), "=r"(r[2]), "=r"(r[3]) : "r"(addr));
}
__device__ __forceinline__ void mma16816(float* c,
                                         const uint32_t* a,
                                         uint32_t b0, uint32_t b1) {
    asm volatile(
        "mma.sync.aligned.m16n8k16.row.col.f32.f16.f16.f32 "
        "{%0,%1,%2,%3}, {%4,%5,%6,%7}, {%8,%9}, {%0,%1,%2,%3};"
        : "+f"(c[0]), "+f"(c[1]), "+f"(c[2]), "+f"(c[3])
        : "r"(a[0]), "r"(a[1]), "r"(a[2]), "r"(a[3]), "r"(b0), "r"(b1));
}

// ---------------- prep kernel (coalesced only) --------------------------------
__global__ void prep_W(const float* __restrict__ W) {
    int i = blockIdx.x * blockDim.x + threadIdx.x;
    if (i == 0) g_ncand = 0;
    g_Whi[i] = __float2half_rn(W[i] * 64.0f);
}

// ---------------- producer helpers (pt in [0,128)) ----------------------------
// issue cp.async for x chunk c (32 KB) into slot, + W chunk c into wslot
__device__ __forceinline__ void cpXW_chunk(uint32_t sbase, const float* __restrict__ x,
                                           int row0, int c, int pt) {
    const int slot  = c % 3;
    const int wslot = c % 4;
    const int c0 = c * KC;
#pragma unroll
    for (int it = 0; it < 16; ++it) {
        int id = it * 128 + pt;          // 0..2047
        int row = id >> 4, seg = id & 15;
        uint32_t dst = sbase + SM_XS(slot) + (uint32_t)(row * 272 + seg * 16);
        cp16(dst, x + (size_t)(row0 + row) * D_DIM + c0 + seg * 4);
    }
#pragma unroll
    for (int it = 0; it < 4; ++it) {
        int id = it * 128 + pt;          // 0..511
        int e = id >> 3, q = id & 7;
        uint32_t dst = sbase + SM_W(wslot) + SWZ(e * 128 + q * 16);
        cp16(dst, g_Whi + (size_t)e * D_DIM + c0 + q * 8);
    }
    cp_commit();
}

// convert x chunk (f32 in smem slot) -> fp16 A tile buf
__device__ __forceinline__ void convert_chunk(char* smem, int c, int pt) {
    const float* xs = (const float*)(smem + SM_XS(c % 3));
    char* dst = smem + SM_A(c & 1);
#pragma unroll
    for (int it = 0; it < 8; ++it) {
        int id = it * 128 + pt;
        int row = id >> 3, g = id & 7;
        const float* p = xs + row * 68 + g * 8;
        float4 a = *(const float4*)p;
        float4 b = *(const float4*)(p + 4);
        __half2 h0 = __floats2half2_rn(a.x * 16.0f, a.y * 16.0f);
        __half2 h1 = __floats2half2_rn(a.z * 16.0f, a.w * 16.0f);
        __half2 h2 = __floats2half2_rn(b.x * 16.0f, b.y * 16.0f);
        __half2 h3 = __floats2half2_rn(b.z * 16.0f, b.w * 16.0f);
        uint32_t off = SWZ(row * 128 + g * 16);
        *(uint4*)(dst + off) = make_uint4(
            *reinterpret_cast<uint32_t*>(&h0), *reinterpret_cast<uint32_t*>(&h1),
            *reinterpret_cast<uint32_t*>(&h2), *reinterpret_cast<uint32_t*>(&h3));
    }
}

// ---------------- main kernel -------------------------------------------------
__global__ void __launch_bounds__(THREADS, 1)
router_kernel(const float* __restrict__ x, float* __restrict__ out)
{
    extern __shared__ char smem[];
    const int t    = threadIdx.x;
    const int lane = t & 31;
    const int row0 = blockIdx.x * ROWS_PER_BLK;
    const uint32_t sbase = (uint32_t)__cvta_generic_to_shared(smem);
    const bool consumer = (t < 128);

    const int lg = lane >> 3;
    const int li = lane & 7;

    const int wc = t >> 5;                    // 0..3 consumers, rows [32wc,+32)
    float acc[2][8][4];
#pragma unroll
    for (int m = 0; m < 2; ++m)
#pragma unroll
        for (int j = 0; j < 8; ++j)
#pragma unroll
            for (int q = 0; q < 4; ++q) acc[m][j][q] = 0.f;

    uint32_t aoffb[2];
#pragma unroll
    for (int m = 0; m < 2; ++m) {
        int arow = 32 * wc + 16 * m + li + ((lg & 1) ? 8 : 0);
        aoffb[m] = (uint32_t)(arow * 128 + ((lg & 2) ? 16 : 0));
    }
    const int berow = li + ((lg & 2) ? 8 : 0);
    const uint32_t boffb = (uint32_t)(berow * 128 + ((lg & 1) ? 16 : 0));

    const int pt = t - 128;

    // ---- prologue ----
    if (!consumer) {
        cpXW_chunk(sbase, x, row0, 0, pt);   // G0
        cpXW_chunk(sbase, x, row0, 1, pt);   // G1
        cp_wait1();                          // G0 done (this thread's)
    }
    __syncthreads();                         // G0 data visible CTA-wide
    if (!consumer) {
        convert_chunk(smem, 0, pt);          // A0
        cpXW_chunk(sbase, x, row0, 2, pt);   // G2
        cp_wait1();                          // G1 done
    }
    __syncthreads();                         // G1 visible; A0 visible

    // ---- main loop ----
    for (int c = 0; c < NCHUNK; ++c) {
        if (consumer) {
            const uint32_t ahi = sbase + SM_A(c & 1);
            const uint32_t whi = sbase + SM_W(c % 4);

            uint32_t fw[2][4][4];
#pragma unroll
            for (int p = 0; p < 4; ++p)
                ldsm4(whi + SWZ(boffb + (uint32_t)(p * 16 * 128)), fw[0][p]);
#pragma unroll
            for (int s = 0; s < 4; ++s) {
                uint32_t fa[2][4];
#pragma unroll
                for (int m = 0; m < 2; ++m)
                    ldsm4(ahi + SWZ(aoffb[m] + s * 32), fa[m]);
                if (s < 3) {
#pragma unroll
                    for (int p = 0; p < 4; ++p)
                        ldsm4(whi + SWZ(boffb + (uint32_t)(p * 16 * 128) + (s + 1) * 32),
                              fw[(s + 1) & 1][p]);
                }
#pragma unroll
                for (int p = 0; p < 4; ++p) {
                    const uint32_t* bh = fw[s & 1][p];
#pragma unroll
                    for (int m = 0; m < 2; ++m) {
                        mma16816(acc[m][2 * p],     fa[m], bh[0], bh[1]);
                        mma16816(acc[m][2 * p + 1], fa[m], bh[2], bh[3]);
                    }
                }
            }
        } else {
            if (c + 1 < NCHUNK) convert_chunk(smem, c + 1, pt);   // uses G(c+1), visible
            if (c + 3 < NCHUNK) {
                cpXW_chunk(sbase, x, row0, c + 3, pt);            // G(c+3)
                cp_wait1();                                       // G(c+2) done
            } else {
                cp_wait0();                                       // drain tail
            }
        }
        __syncthreads();
    }

    // ---- epilogue: logits -> smem (reuse XS region) ----
    float* lgm = (float*)smem;
    if (consumer) {
        const int r_in = lane >> 2;
        const int col  = 2 * (lane & 3);
        const float sc = 1.0f / 1024.0f;
#pragma unroll
        for (int m = 0; m < 2; ++m) {
            const int rb = 32 * wc + 16 * m + r_in;
#pragma unroll
            for (int j = 0; j < 8; ++j) {
                *(float2*)(lgm + rb * LG_STRIDE + 8 * j + col)
                    = make_float2(acc[m][j][0] * sc, acc[m][j][1] * sc);
                *(float2*)(lgm + (rb + 8) * LG_STRIDE + 8 * j + col)
                    = make_float2(acc[m][j][2] * sc, acc[m][j][3] * sc);
            }
        }
    }
    __syncthreads();

    if (t < ROWS_PER_BLK) {
        float l[64];
#pragma unroll
        for (int j = 0; j < 16; ++j) {
            float4 v = *(const float4*)(lgm + t * LG_STRIDE + 4 * j);
            l[4*j+0] = v.x; l[4*j+1] = v.y; l[4*j+2] = v.z; l[4*j+3] = v.w;
        }

        float mx = l[0];
#pragma unroll
        for (int j = 1; j < 64; ++j) mx = fmaxf(mx, l[j]);

        float v1 = -3.4e38f, v2 = -3.4e38f, v3 = -3.4e38f;
        int   i1 = 0,        i2 = 0;
#pragma unroll
        for (int j = 0; j < 64; ++j) {
            float lj = l[j];
            if (lj > v1)      { v3 = v2; v2 = v1; i2 = i1; v1 = lj; i1 = j; }
            else if (lj > v2) { v3 = v2; v2 = lj; i2 = j; }
            else if (lj > v3) { v3 = lj; }
        }

        float p[64], s = 0.f;
#pragma unroll
        for (int j = 0; j < 64; ++j) { p[j] = __expf(l[j] - mx); s += p[j]; }
        float inv = __fdividef(1.0f, s);

        const int grow = row0 + t;
        float* po = out + (size_t)grow * 64;
#pragma unroll
        for (int j = 0; j < 16; ++j) {
            float4 v;
            v.x = p[4*j+0] * inv; v.y = p[4*j+1] * inv;
            v.z = p[4*j+2] * inv; v.w = p[4*j+3] * inv;
            *(float4*)(po + 4 * j) = v;
        }
        float* io = out + (size_t)NROWS * 64;
        io[(size_t)grow * 2 + 0] = (float)i1;
        io[(size_t)grow * 2 + 1] = (float)i2;
        float* vo = out + (size_t)NROWS * 64 + (size_t)NROWS * 2;
        vo[(size_t)grow * 2 + 0] = __expf(v1 - mx) * inv;
        vo[(size_t)grow * 2 + 1] = __expf(v2 - mx) * inv;

        if ((v1 - v2) < GAP_T || (v2 - v3) < GAP_T) {
            int slot = atomicAdd(&g_ncand, 1);
            g_cand[slot] = grow;
        }
    }
}

// ---------------- fixup: one warp per flagged row ------------------------------
__global__ void __launch_bounds__(256, 1)
fixup_kernel(const float* __restrict__ x, const float* __restrict__ W,
             float* __restrict__ out)
{
    const int n    = g_ncand;
    const int lane = threadIdx.x & 31;
    const int gw   = (blockIdx.x * blockDim.x + threadIdx.x) >> 5;
    const int nw   = (gridDim.x * blockDim.x) >> 5;

    for (int ci = gw; ci < n; ci += nw) {
        const int row = g_cand[ci];
        const float* probs = out + (size_t)row * 64;

        float p0 = probs[lane];
        float p1 = probs[lane + 32];

        float m1 = fmaxf(p0, p1), m2 = fminf(p0, p1);
#pragma unroll
        for (int o = 16; o > 0; o >>= 1) {
            float o1 = __shfl_xor_sync(0xFFFFFFFF, m1, o);
            float o2 = __shfl_xor_sync(0xFFFFFFFF, m2, o);
            float n1 = fmaxf(m1, o1);
            float n2 = fminf(fmaxf(m1, o2), fmaxf(o1, m2));
            n2 = fmaxf(n2, fminf(m1, o1));
            m1 = n1; m2 = n2;
        }
        const float thresh = m2 * BAND_MUL;

        unsigned b0 = __ballot_sync(0xFFFFFFFF, p0 >= thresh);
        unsigned b1 = __ballot_sync(0xFFFFFFFF, p1 >= thresh);

        const float4* xr = (const float4*)(x + (size_t)row * D_DIM);

        float best1 = -3.4e38f, best2 = -3.4e38f;
        int   bi1 = -1,         bi2 = -1;

        for (int e = 0; e < 64; ++e) {
            bool cand = (e < 32) ? ((b0 >> e) & 1u) : ((b1 >> (e - 32)) & 1u);
            if (!cand) continue;
            const float4* wr = (const float4*)(W + (size_t)e * D_DIM);
            float a0 = 0.f, a1 = 0.f;
            for (int i = lane; i < D_DIM / 4; i += 64) {
                float4 xv = xr[i],      wv = wr[i];
                float4 xu = xr[i + 32], wu = wr[i + 32];
                a0 += xv.x * wv.x; a0 += xv.y * wv.y;
                a0 += xv.z * wv.z; a0 += xv.w * wv.w;
                a1 += xu.x * wu.x; a1 += xu.y * wu.y;
                a1 += xu.z * wu.z; a1 += xu.w * wu.w;
            }
            float a = a0 + a1;
#pragma unroll
            for (int o = 16; o > 0; o >>= 1)
                a += __shfl_xor_sync(0xFFFFFFFF, a, o);
            if (a > best1)      { best2 = best1; bi2 = bi1; best1 = a; bi1 = e; }
            else if (a > best2) { best2 = a; bi2 = e; }
        }

        if (lane == 0) {
            float* io = out + (size_t)NROWS * 64;
            io[(size_t)row * 2 + 0] = (float)bi1;
            io[(size_t)row * 2 + 1] = (float)bi2;
            float* vo = out + (size_t)NROWS * 64 + (size_t)NROWS * 2;
            vo[(size_t)row * 2 + 0] = probs[bi1];
            vo[(size_t)row * 2 + 1] = probs[bi2];
        }
    }
}

// ---------------------------------------------------------------------------
extern "C" void kernel_launch(void* const* d_in, const int* in_sizes, int n_in,
                              void* d_out, int out_size) {
    const float* x = (const float*)d_in[0];
    const float* W = (const float*)d_in[1];
    float* out = (float*)d_out;

    prep_W<<<(E_DIM * D_DIM) / 256, 256>>>(W);

    cudaFuncSetAttribute(router_kernel,
                         cudaFuncAttributeMaxDynamicSharedMemorySize, SMEM_BYTES);
    router_kernel<<<NROWS / ROWS_PER_BLK, THREADS, SMEM_BYTES>>>(x, out);

    fixup_kernel<<<256, 256>>>(x, W, out);
}